// round 1
// baseline (speedup 1.0000x reference)
#include <cuda_runtime.h>

#define BB 4
#define PP 2048
#define EE 1024
#define HH 16
#define HD 64

// Scratch (fully overwritten every launch; deterministic)
__device__ __align__(16) float g_Qs[BB*HH*PP];      // row-sums of Q per head  [b][h][p]
__device__ __align__(16) float g_Ks[BB*HH*PP];      // row-sums of K per head  [b][h][p]
__device__ __align__(16) float g_Vpart[BB*8*EE];    // partial column sums of V
__device__ __align__(16) float g_Ut[BB*EE*HH];      // U transposed: [b][n][h]
__device__ __align__(16) float g_diag[BB*HH*PP];    // softmax diagonal [b][h][p]

__device__ __forceinline__ float ex2f(float x){
    float y; asm("ex2.approx.ftz.f32 %0, %1;" : "=f"(y) : "f"(x)); return y;
}

// ---------------------------------------------------------------------------
// K1: Qs/Ks head row-sums + V partial column sums.  Streams 96 MB (HBM-bound).
//   blocks [0,8192): Q sums, [8192,16384): K sums, [16384,16512): V partials.
// ---------------------------------------------------------------------------
__global__ void k_reduce(const float* __restrict__ Q, const float* __restrict__ K,
                         const float* __restrict__ V) {
    int bid = blockIdx.x;
    int tid = threadIdx.x;
    if (bid < 16384) {
        const float* src; float* dst; int base;
        if (bid < 8192) { src = Q; dst = g_Qs; base = bid; }
        else            { src = K; dst = g_Ks; base = bid - 8192; }
        // 16 segments per block, 16 threads per segment (64 contiguous floats)
        int seg    = base * 16 + (tid >> 4);
        int lane16 = tid & 15;
        int h  = seg & 15;
        int bp = seg >> 4;                       // b*2048 + p
        float4 v = ((const float4*)(src + ((size_t)bp << 10) + h * HD))[lane16];
        float s = (v.x + v.y) + (v.z + v.w);
        s += __shfl_down_sync(0xffffffffu, s, 8, 16);
        s += __shfl_down_sync(0xffffffffu, s, 4, 16);
        s += __shfl_down_sync(0xffffffffu, s, 2, 16);
        s += __shfl_down_sync(0xffffffffu, s, 1, 16);
        if (lane16 == 0) {
            int b = bp >> 11, p = bp & 2047;
            dst[((b * HH + h) << 11) + p] = s;
        }
    } else {
        // V partial column sums: 128 blocks, each sums 256 rows x 256 cols
        int blk = bid - 16384;
        int b = blk >> 5, r = blk & 31, pc = r >> 2, cg = r & 3;
        int c = cg * 256 + tid;
        const float* base = V + ((size_t)b * PP + pc * 256) * EE + c;
        float s = 0.f;
        #pragma unroll 8
        for (int p = 0; p < 256; p++) s += base[(size_t)p * EE];
        g_Vpart[(b * 8 + pc) * EE + c] = s;
    }
}

// ---------------------------------------------------------------------------
// K2: reduce V partials -> Vs, then U[b][n][h] = sum_e Vs[b,h,e]*W[n, h*64+e].
//   64 blocks (b,h), 256 threads.
// ---------------------------------------------------------------------------
__global__ void k_proj_u(const float* __restrict__ W) {
    int b = blockIdx.x >> 4, h = blockIdx.x & 15;
    __shared__ float vs[HD];
    int tid = threadIdx.x;
    if (tid < HD) {
        float s = 0.f;
        #pragma unroll
        for (int pc = 0; pc < 8; pc++) s += g_Vpart[(b * 8 + pc) * EE + h * HD + tid];
        vs[tid] = s;
    }
    __syncthreads();
    for (int n = tid; n < EE; n += 256) {
        const float4* wr = (const float4*)(W + (size_t)n * EE + h * HD);
        float acc = 0.f;
        #pragma unroll
        for (int e = 0; e < 16; e++) {
            float4 w = wr[e];
            acc += w.x * vs[4*e] + w.y * vs[4*e+1] + w.z * vs[4*e+2] + w.w * vs[4*e+3];
        }
        g_Ut[((size_t)((b << 10) + n)) * HH + h] = acc;
    }
}

// ---------------------------------------------------------------------------
// K3: the heavy kernel. For each (b,h,i): denom_i = sum_j exp2(alpha_i*ks_j - M)
//   and diag_i = exp2(alpha_i*ks_i - M)/denom_i.  268M ex2 -> MUFU-bound.
//   grid 512 = 64 (b,h) x 8 i-chunks; 256 threads = one i per thread.
// ---------------------------------------------------------------------------
__global__ void k_softmax_diag() {
    int bh = blockIdx.x >> 3, ic = blockIdx.x & 7;
    __shared__ __align__(16) float ks[PP];
    __shared__ float rmn[8], rmx[8];
    __shared__ float s_mn, s_mx;
    int tid = threadIdx.x;
    const float4* kr4 = (const float4*)(g_Ks + ((size_t)bh << 11));
    float4* ks4 = (float4*)ks;
    float mn = 3.4e38f, mx = -3.4e38f;
    #pragma unroll
    for (int i = 0; i < 2; i++) {
        int idx = i * 256 + tid;
        float4 v = kr4[idx];
        ks4[idx] = v;
        mn = fminf(mn, fminf(fminf(v.x, v.y), fminf(v.z, v.w)));
        mx = fmaxf(mx, fmaxf(fmaxf(v.x, v.y), fmaxf(v.z, v.w)));
    }
    #pragma unroll
    for (int off = 16; off; off >>= 1) {
        mn = fminf(mn, __shfl_xor_sync(0xffffffffu, mn, off));
        mx = fmaxf(mx, __shfl_xor_sync(0xffffffffu, mx, off));
    }
    if ((tid & 31) == 0) { rmn[tid >> 5] = mn; rmx[tid >> 5] = mx; }
    __syncthreads();
    if (tid == 0) {
        float a = rmn[0], c = rmx[0];
        #pragma unroll
        for (int w = 1; w < 8; w++) { a = fminf(a, rmn[w]); c = fmaxf(c, rmx[w]); }
        s_mn = a; s_mx = c;
    }
    __syncthreads();

    const float C = 0.125f * 1.44269504088896340736f;   // sm_scale * log2(e)
    float alpha = g_Qs[((size_t)bh << 11) + (ic << 8) + tid] * C;
    float nM = -((alpha >= 0.f) ? alpha * s_mx : alpha * s_mn);

    float acc[8];
    #pragma unroll
    for (int u = 0; u < 8; u++) acc[u] = 0.f;
    #pragma unroll 4
    for (int j = 0; j < PP; j += 8) {
        float4 x = ks4[j >> 2];
        float4 y = ks4[(j >> 2) + 1];
        acc[0] += ex2f(fmaf(alpha, x.x, nM));
        acc[1] += ex2f(fmaf(alpha, x.y, nM));
        acc[2] += ex2f(fmaf(alpha, x.z, nM));
        acc[3] += ex2f(fmaf(alpha, x.w, nM));
        acc[4] += ex2f(fmaf(alpha, y.x, nM));
        acc[5] += ex2f(fmaf(alpha, y.y, nM));
        acc[6] += ex2f(fmaf(alpha, y.z, nM));
        acc[7] += ex2f(fmaf(alpha, y.w, nM));
    }
    float denom = ((acc[0] + acc[1]) + (acc[2] + acc[3]))
                + ((acc[4] + acc[5]) + (acc[6] + acc[7]));
    int i = (ic << 8) + tid;
    float num = ex2f(fmaf(alpha, ks[i], nM));
    g_diag[((size_t)bh << 11) + i] = num / denom;
}

// ---------------------------------------------------------------------------
// K4: Y[b,p,n] = sum_h diag[b,h,p] * Ut[b,n,h] + bias[n].  Writes 32 MB.
//   grid 512 = 4b x 32 p-tiles(64) x 4 n-quarters(256); 256 threads, 1 n each.
// ---------------------------------------------------------------------------
__global__ void k_out(const float* __restrict__ bias, float* __restrict__ Y) {
    int nq = blockIdx.x & 3;
    int pt = (blockIdx.x >> 2) & 31;
    int b  = blockIdx.x >> 7;
    int tid = threadIdx.x;
    __shared__ float dsm[HH * 64];
    #pragma unroll
    for (int hh = 0; hh < 4; hh++) {
        int h  = hh * 4 + (tid >> 6);
        int pl = tid & 63;
        dsm[h * 64 + pl] = g_diag[((size_t)((b * HH + h)) << 11) + pt * 64 + pl];
    }
    __syncthreads();
    int n = (nq << 8) + tid;
    float u[16];
    const float4* up = (const float4*)(g_Ut + ((size_t)((b << 10) + n)) * HH);
    #pragma unroll
    for (int q = 0; q < 4; q++) {
        float4 v = up[q];
        u[4*q] = v.x; u[4*q+1] = v.y; u[4*q+2] = v.z; u[4*q+3] = v.w;
    }
    float bn = bias[n];
    float* out = Y + (((size_t)(b * PP + pt * 64)) << 10) + n;
    #pragma unroll 4
    for (int p = 0; p < 64; p++) {
        float acc = bn;
        #pragma unroll
        for (int h = 0; h < 16; h++) acc = fmaf(u[h], dsm[h * 64 + p], acc);
        out[((size_t)p) << 10] = acc;
    }
}

extern "C" void kernel_launch(void* const* d_in, const int* in_sizes, int n_in,
                              void* d_out, int out_size) {
    const float* Q    = (const float*)d_in[0];
    const float* K    = (const float*)d_in[1];
    const float* V    = (const float*)d_in[2];
    const float* W    = (const float*)d_in[3];
    const float* bias = (const float*)d_in[4];
    float* Y = (float*)d_out;

    k_reduce<<<16512, 256>>>(Q, K, V);
    k_proj_u<<<64, 256>>>(W);
    k_softmax_diag<<<512, 256>>>();
    k_out<<<512, 256>>>(bias, Y);
}

// round 4
// speedup vs baseline: 1.5333x; 1.5333x over previous
#include <cuda_runtime.h>

#define BB 4
#define PP 2048
#define EE 1024
#define HH 16
#define HD 64
#define NBIN 256
#define NPART 8

// Scratch (fully overwritten every launch; deterministic up to shared-atomic
// float ordering in k_bin, whose contribution is ~1e-7 — far under tolerance)
__device__ __align__(16) float g_Qs[BB*HH*PP];
__device__ __align__(16) float g_Ks[BB*HH*PP];
__device__ __align__(16) float g_Vpart[BB*8*EE];
__device__ __align__(16) float g_Ut[BB*EE*HH];
__device__ __align__(16) float g_diag[BB*HH*PP];
// partial bin tables: [bh][part][coef(5)][bin(256)]
__device__ __align__(16) float g_bt[BB*HH*NPART*5*NBIN];

__device__ __forceinline__ float ex2f(float x){
    float y; asm("ex2.approx.ftz.f32 %0, %1;" : "=f"(y) : "f"(x)); return y;
}

// ---------------------------------------------------------------------------
// K1: Qs/Ks head row-sums + V partial column sums. Streams 96 MB.
// ---------------------------------------------------------------------------
__global__ void k_reduce(const float* __restrict__ Q, const float* __restrict__ K,
                         const float* __restrict__ V) {
    int bid = blockIdx.x;
    int tid = threadIdx.x;
    if (bid < 16384) {
        const float* src; float* dst; int base;
        if (bid < 8192) { src = Q; dst = g_Qs; base = bid; }
        else            { src = K; dst = g_Ks; base = bid - 8192; }
        int seg    = base * 16 + (tid >> 4);
        int lane16 = tid & 15;
        int h  = seg & 15;
        int bp = seg >> 4;
        float4 v = ((const float4*)(src + ((size_t)bp << 10) + h * HD))[lane16];
        float s = (v.x + v.y) + (v.z + v.w);
        s += __shfl_down_sync(0xffffffffu, s, 8, 16);
        s += __shfl_down_sync(0xffffffffu, s, 4, 16);
        s += __shfl_down_sync(0xffffffffu, s, 2, 16);
        s += __shfl_down_sync(0xffffffffu, s, 1, 16);
        if (lane16 == 0) {
            int b = bp >> 11, p = bp & 2047;
            dst[((b * HH + h) << 11) + p] = s;
        }
    } else {
        int blk = bid - 16384;
        int b = blk >> 5, r = blk & 31, pc = r >> 2, cg = r & 3;
        int c = cg * 256 + tid;
        const float* base = V + ((size_t)b * PP + pc * 256) * EE + c;
        float s = 0.f;
        #pragma unroll 8
        for (int p = 0; p < 256; p++) s += base[(size_t)p * EE];
        g_Vpart[(b * 8 + pc) * EE + c] = s;
    }
}

// ---------------------------------------------------------------------------
// K2: Vs -> U[b][n][h]
// ---------------------------------------------------------------------------
__global__ void k_proj_u(const float* __restrict__ W) {
    int b = blockIdx.x >> 4, h = blockIdx.x & 15;
    __shared__ float vs[HD];
    int tid = threadIdx.x;
    if (tid < HD) {
        float s = 0.f;
        #pragma unroll
        for (int pc = 0; pc < 8; pc++) s += g_Vpart[(b * 8 + pc) * EE + h * HD + tid];
        vs[tid] = s;
    }
    __syncthreads();
    for (int n = tid; n < EE; n += 256) {
        const float4* wr = (const float4*)(W + (size_t)n * EE + h * HD);
        float acc = 0.f;
        #pragma unroll
        for (int e = 0; e < 16; e++) {
            float4 w = wr[e];
            acc += w.x * vs[4*e] + w.y * vs[4*e+1] + w.z * vs[4*e+2] + w.w * vs[4*e+3];
        }
        g_Ut[((size_t)((b << 10) + n)) * HH + h] = acc;
    }
}

// ---------------------------------------------------------------------------
// min/max of ks[2048] for one bh, exact (order-independent). 256 threads.
// ---------------------------------------------------------------------------
__device__ __forceinline__ void ks_minmax(const float4* kr4, int tid,
                                          float* s_mn, float* s_mx) {
    __shared__ float rmn[8], rmx[8];
    float mn = 3.4e38f, mx = -3.4e38f;
    #pragma unroll
    for (int i = 0; i < 2; i++) {
        float4 v = kr4[i * 256 + tid];
        mn = fminf(mn, fminf(fminf(v.x, v.y), fminf(v.z, v.w)));
        mx = fmaxf(mx, fmaxf(fmaxf(v.x, v.y), fmaxf(v.z, v.w)));
    }
    #pragma unroll
    for (int off = 16; off; off >>= 1) {
        mn = fminf(mn, __shfl_xor_sync(0xffffffffu, mn, off));
        mx = fmaxf(mx, __shfl_xor_sync(0xffffffffu, mx, off));
    }
    if ((tid & 31) == 0) { rmn[tid >> 5] = mn; rmx[tid >> 5] = mx; }
    __syncthreads();
    if (tid == 0) {
        float a = rmn[0], c = rmx[0];
        #pragma unroll
        for (int w = 1; w < 8; w++) { a = fminf(a, rmn[w]); c = fmaxf(c, rmx[w]); }
        *s_mn = a; *s_mx = c;
    }
    __syncthreads();
}

// ---------------------------------------------------------------------------
// K_bin: build partial moment tables. grid 512 = 64bh x 8 parts, 256 thr.
//   coefs: c0=n, c1=Sum d, c2=Sum d^2/2, c3=Sum d^3/6, c4=Sum d^4/24
// ---------------------------------------------------------------------------
__global__ void k_bin() {
    int bh = blockIdx.x >> 3, part = blockIdx.x & 7;
    int tid = threadIdx.x;
    __shared__ float s_mn, s_mx;
    __shared__ float tb[5][NBIN];
    const float4* kr4 = (const float4*)(g_Ks + ((size_t)bh << 11));
    ks_minmax(kr4, tid, &s_mn, &s_mx);
    #pragma unroll
    for (int c = 0; c < 5; c++) tb[c][tid] = 0.f;
    __syncthreads();

    float mn = s_mn, mx = s_mx;
    float w = fmaxf(mx - mn, 1e-20f) * (1.0f / NBIN);
    float invw = 1.0f / w;

    float k = g_Ks[((size_t)bh << 11) + (part << 8) + tid];
    int idx = (int)((k - mn) * invw);
    idx = max(0, min(NBIN - 1, idx));
    float kb = mn + ((float)idx + 0.5f) * w;
    float d  = k - kb;
    float d2 = d * d;
    atomicAdd(&tb[0][idx], 1.0f);
    atomicAdd(&tb[1][idx], d);
    atomicAdd(&tb[2][idx], 0.5f * d2);
    atomicAdd(&tb[3][idx], d * d2 * (1.0f / 6.0f));
    atomicAdd(&tb[4][idx], d2 * d2 * (1.0f / 24.0f));
    __syncthreads();

    float* out = g_bt + (size_t)((bh * NPART + part) * 5) * NBIN;
    #pragma unroll
    for (int c = 0; c < 5; c++) out[c * NBIN + tid] = tb[c][tid];
}

// ---------------------------------------------------------------------------
// K3: softmax diagonal via binned moment expansion. 256 bins instead of
//   2048 exps per i: denom_i = Sum_b exp(a*kb)*(c0 + a(c1 + a(c2 + a(c3+a c4))))
//   grid 512 = 64bh x 8 chunks, 256 threads (one i each).
// ---------------------------------------------------------------------------
__global__ void k_softmax_diag() {
    int bh = blockIdx.x >> 3, ic = blockIdx.x & 7;
    int tid = threadIdx.x;
    __shared__ __align__(16) float ks[PP];
    __shared__ float s_mn, s_mx;
    __shared__ __align__(16) float4 cf4[NBIN];
    __shared__ float cf0[NBIN];

    const float4* kr4 = (const float4*)(g_Ks + ((size_t)bh << 11));
    float4* ks4 = (float4*)ks;
    // stage ks into smem while computing min/max
    {
        float4 a = kr4[tid], b = kr4[256 + tid];
        ks4[tid] = a; ks4[256 + tid] = b;
    }
    ks_minmax(kr4, tid, &s_mn, &s_mx);

    // sum the 8 partial tables (each thread owns one bin)
    {
        const float* bt = g_bt + (size_t)(bh * NPART * 5) * NBIN + tid;
        float c0 = 0, c1 = 0, c2 = 0, c3 = 0, c4 = 0;
        #pragma unroll
        for (int part = 0; part < NPART; part++) {
            const float* p = bt + (size_t)(part * 5) * NBIN;
            c0 += p[0];
            c1 += p[NBIN];
            c2 += p[2 * NBIN];
            c3 += p[3 * NBIN];
            c4 += p[4 * NBIN];
        }
        cf0[tid] = c0;
        cf4[tid] = make_float4(c1, c2, c3, c4);
    }
    __syncthreads();

    float mn = s_mn, mx = s_mx;
    float w = fmaxf(mx - mn, 1e-20f) * (1.0f / NBIN);

    const float L2E = 1.44269504088896340736f;
    float a  = 0.125f * g_Qs[((size_t)bh << 11) + (ic << 8) + tid];  // natural
    float a2 = a * L2E;                                              // exp2 dom
    float nM = -((a2 >= 0.f) ? a2 * mx : a2 * mn);

    float acc0 = 0.f, acc1 = 0.f;
    float kb0 = mn + 0.5f * w;
    float kb1 = kb0 + 128.0f * w;
    #pragma unroll 4
    for (int b = 0; b < 128; b++) {
        {
            float e = ex2f(fmaf(a2, kb0, nM));
            float4 c = cf4[b];
            float p = fmaf(a, c.w, c.z);
            p = fmaf(a, p, c.y);
            p = fmaf(a, p, c.x);
            p = fmaf(a, p, cf0[b]);
            acc0 = fmaf(e, p, acc0);
        }
        {
            float e = ex2f(fmaf(a2, kb1, nM));
            float4 c = cf4[b + 128];
            float p = fmaf(a, c.w, c.z);
            p = fmaf(a, p, c.y);
            p = fmaf(a, p, c.x);
            p = fmaf(a, p, cf0[b + 128]);
            acc1 = fmaf(e, p, acc1);
        }
        kb0 += w; kb1 += w;
    }
    float denom = acc0 + acc1;

    int i = (ic << 8) + tid;
    float num = ex2f(fmaf(a2, ks[i], nM));
    g_diag[((size_t)bh << 11) + i] = num / denom;
}

// ---------------------------------------------------------------------------
// K4: Y[b,p,n] = sum_h diag[b,h,p] * Ut[b,n,h] + bias[n].
//   Register-tiled rank-16 GEMM: 256 threads x 4 consecutive n (STG.128),
//   p-tile 32; grid 256 = 4b x 64 p-tiles.
// ---------------------------------------------------------------------------
__global__ void __launch_bounds__(256) k_out(const float* __restrict__ bias,
                                             float* __restrict__ Y) {
    int pt = blockIdx.x & 63;
    int b  = blockIdx.x >> 6;
    int tid = threadIdx.x;
    __shared__ float dsm[HH * 32];
    #pragma unroll
    for (int r = 0; r < 2; r++) {
        int idx = r * 256 + tid;
        int h = idx >> 5, pl = idx & 31;
        dsm[h * 32 + pl] = g_diag[(((size_t)(b * HH + h)) << 11) + pt * 32 + pl];
    }
    __syncthreads();

    int n0 = tid << 2;
    float4 u4[HH];
    {
        const float4* up = (const float4*)(g_Ut + ((size_t)((b << 10) + n0)) * HH);
        float un[4][HH];
        #pragma unroll
        for (int nn = 0; nn < 4; nn++) {
            #pragma unroll
            for (int q = 0; q < 4; q++) {
                float4 v = up[nn * 4 + q];
                un[nn][4*q] = v.x; un[nn][4*q+1] = v.y;
                un[nn][4*q+2] = v.z; un[nn][4*q+3] = v.w;
            }
        }
        #pragma unroll
        for (int h = 0; h < HH; h++)
            u4[h] = make_float4(un[0][h], un[1][h], un[2][h], un[3][h]);
    }
    float4 bn = *(const float4*)(bias + n0);

    float4* out = (float4*)(Y + (((size_t)(b * PP + pt * 32)) << 10) + n0);
    #pragma unroll 2
    for (int p = 0; p < 32; p++) {
        float4 acc = bn;
        #pragma unroll
        for (int h = 0; h < HH; h++) {
            float d = dsm[h * 32 + p];
            acc.x = fmaf(u4[h].x, d, acc.x);
            acc.y = fmaf(u4[h].y, d, acc.y);
            acc.z = fmaf(u4[h].z, d, acc.z);
            acc.w = fmaf(u4[h].w, d, acc.w);
        }
        out[(size_t)p << 8] = acc;
    }
}

extern "C" void kernel_launch(void* const* d_in, const int* in_sizes, int n_in,
                              void* d_out, int out_size) {
    const float* Q    = (const float*)d_in[0];
    const float* K    = (const float*)d_in[1];
    const float* V    = (const float*)d_in[2];
    const float* W    = (const float*)d_in[3];
    const float* bias = (const float*)d_in[4];
    float* Y = (float*)d_out;

    k_reduce<<<16512, 256>>>(Q, K, V);
    k_bin<<<512, 256>>>();
    k_proj_u<<<64, 256>>>(W);
    k_softmax_diag<<<512, 256>>>();
    k_out<<<256, 256>>>(bias, Y);
}

// round 5
// speedup vs baseline: 1.7257x; 1.1254x over previous
#include <cuda_runtime.h>

#define BB 4
#define PP 2048
#define EE 1024
#define HH 16
#define HD 64
#define NBIN 256
#define NPART 8
#define NVP 32          // V partial chunks per batch

// Scratch (fully overwritten every launch)
__device__ __align__(16) float g_Qs[BB*HH*PP];
__device__ __align__(16) float g_Ks[BB*HH*PP];
__device__ __align__(16) float g_Vpart[BB*NVP*EE];
__device__ __align__(16) float g_Ut[BB*EE*HH];
__device__ __align__(16) float g_diag[BB*HH*PP];
__device__ __align__(16) float g_bt[BB*HH*NPART*5*NBIN];  // [bh][part][coef5][bin]
__device__ __align__(8)  float2 g_mnmx[BB*HH];

__device__ __forceinline__ float ex2f(float x){
    float y; asm("ex2.approx.ftz.f32 %0, %1;" : "=f"(y) : "f"(x)); return y;
}

// ---------------------------------------------------------------------------
// K1: Qs/Ks head row-sums + V partial column sums. Streams 96 MB.
//   blocks [0,8192): Q, [8192,16384): K, [16384,16896): V (512 blocks).
// ---------------------------------------------------------------------------
__global__ void k_reduce(const float* __restrict__ Q, const float* __restrict__ K,
                         const float* __restrict__ V) {
    int bid = blockIdx.x;
    int tid = threadIdx.x;
    if (bid < 16384) {
        const float* src; float* dst; int base;
        if (bid < 8192) { src = Q; dst = g_Qs; base = bid; }
        else            { src = K; dst = g_Ks; base = bid - 8192; }
        int seg    = base * 16 + (tid >> 4);
        int lane16 = tid & 15;
        int h  = seg & 15;
        int bp = seg >> 4;
        float4 v = ((const float4*)(src + ((size_t)bp << 10) + h * HD))[lane16];
        float s = (v.x + v.y) + (v.z + v.w);
        s += __shfl_down_sync(0xffffffffu, s, 8, 16);
        s += __shfl_down_sync(0xffffffffu, s, 4, 16);
        s += __shfl_down_sync(0xffffffffu, s, 2, 16);
        s += __shfl_down_sync(0xffffffffu, s, 1, 16);
        if (lane16 == 0) {
            int b = bp >> 11, p = bp & 2047;
            dst[((b * HH + h) << 11) + p] = s;
        }
    } else {
        // V partials: 512 blocks, each sums 64 rows x 256 cols
        int blk = bid - 16384;
        int b = blk >> 7, r = blk & 127, pc = r >> 2, cg = r & 3;
        int c = cg * 256 + tid;
        const float* base = V + ((size_t)b * PP + pc * 64) * EE + c;
        float s = 0.f;
        #pragma unroll 16
        for (int p = 0; p < 64; p++) s += base[(size_t)p * EE];
        g_Vpart[(b * NVP + pc) * EE + c] = s;
    }
}

// ---------------------------------------------------------------------------
// min/max of ks[2048] for one bh, exact (order-independent). 256 threads.
// ---------------------------------------------------------------------------
__device__ __forceinline__ void ks_minmax(const float4* kr4, int tid,
                                          float* s_mn, float* s_mx) {
    __shared__ float rmn[8], rmx[8];
    float mn = 3.4e38f, mx = -3.4e38f;
    #pragma unroll
    for (int i = 0; i < 2; i++) {
        float4 v = kr4[i * 256 + tid];
        mn = fminf(mn, fminf(fminf(v.x, v.y), fminf(v.z, v.w)));
        mx = fmaxf(mx, fmaxf(fmaxf(v.x, v.y), fmaxf(v.z, v.w)));
    }
    #pragma unroll
    for (int off = 16; off; off >>= 1) {
        mn = fminf(mn, __shfl_xor_sync(0xffffffffu, mn, off));
        mx = fmaxf(mx, __shfl_xor_sync(0xffffffffu, mx, off));
    }
    if ((tid & 31) == 0) { rmn[tid >> 5] = mn; rmx[tid >> 5] = mx; }
    __syncthreads();
    if (tid == 0) {
        float a = rmn[0], c = rmx[0];
        #pragma unroll
        for (int w = 1; w < 8; w++) { a = fminf(a, rmn[w]); c = fmaxf(c, rmx[w]); }
        *s_mn = a; *s_mx = c;
    }
    __syncthreads();
}

// ---------------------------------------------------------------------------
// K_mid: blocks [0,512) = bin tables (64bh x 8 parts); [512,576) = proj_u.
// ---------------------------------------------------------------------------
__global__ void k_mid(const float* __restrict__ W) {
    int bid = blockIdx.x;
    int tid = threadIdx.x;
    if (bid < 512) {
        int bh = bid >> 3, part = bid & 7;
        __shared__ float s_mn, s_mx;
        __shared__ float tb[5][NBIN];
        const float4* kr4 = (const float4*)(g_Ks + ((size_t)bh << 11));
        ks_minmax(kr4, tid, &s_mn, &s_mx);
        #pragma unroll
        for (int c = 0; c < 5; c++) tb[c][tid] = 0.f;
        __syncthreads();

        float mn = s_mn, mx = s_mx;
        float w = fmaxf(mx - mn, 1e-20f) * (1.0f / NBIN);
        float invw = 1.0f / w;

        float k = g_Ks[((size_t)bh << 11) + (part << 8) + tid];
        int idx = (int)((k - mn) * invw);
        idx = max(0, min(NBIN - 1, idx));
        float kb = mn + ((float)idx + 0.5f) * w;
        float d  = k - kb;
        float d2 = d * d;
        atomicAdd(&tb[0][idx], 1.0f);
        atomicAdd(&tb[1][idx], d);
        atomicAdd(&tb[2][idx], 0.5f * d2);
        atomicAdd(&tb[3][idx], d * d2 * (1.0f / 6.0f));
        atomicAdd(&tb[4][idx], d2 * d2 * (1.0f / 24.0f));
        __syncthreads();

        float* out = g_bt + (size_t)((bh * NPART + part) * 5) * NBIN;
        #pragma unroll
        for (int c = 0; c < 5; c++) out[c * NBIN + tid] = tb[c][tid];
        if (part == 0 && tid == 0) g_mnmx[bh] = make_float2(mn, mx);
    } else {
        int blk = bid - 512;
        int b = blk >> 4, h = blk & 15;
        __shared__ float vs[HD];
        if (tid < HD) {
            float s = 0.f;
            #pragma unroll
            for (int pc = 0; pc < NVP; pc++)
                s += g_Vpart[(b * NVP + pc) * EE + h * HD + tid];
            vs[tid] = s;
        }
        __syncthreads();
        for (int n = tid; n < EE; n += 256) {
            const float4* wr = (const float4*)(W + (size_t)n * EE + h * HD);
            float acc = 0.f;
            #pragma unroll
            for (int e = 0; e < 16; e++) {
                float4 w = wr[e];
                acc += w.x * vs[4*e] + w.y * vs[4*e+1] + w.z * vs[4*e+2] + w.w * vs[4*e+3];
            }
            g_Ut[((size_t)((b << 10) + n)) * HH + h] = acc;
        }
    }
}

// ---------------------------------------------------------------------------
// K3: softmax diagonal via binned moments + geometric e-recurrence.
//   e_{b+1} = e_b * 2^(a2*w); restart via ex2 every 32 bins (FTZ safety).
//   grid 1024 = 64bh x 16 chunks of 128 queries; 128 threads.
// ---------------------------------------------------------------------------
__global__ void __launch_bounds__(128) k_softmax_diag() {
    int bh = blockIdx.x >> 4, ic = blockIdx.x & 15;
    int tid = threadIdx.x;
    __shared__ __align__(16) float4 cf4[NBIN];
    __shared__ float cf0[NBIN];
    __shared__ float2 s_mm;
    if (tid == 0) s_mm = g_mnmx[bh];

    // sum the 8 partial tables (each thread owns 2 bins)
    #pragma unroll
    for (int r = 0; r < 2; r++) {
        int bin = r * 128 + tid;
        const float* bt = g_bt + (size_t)(bh * NPART * 5) * NBIN + bin;
        float c0 = 0, c1 = 0, c2 = 0, c3 = 0, c4 = 0;
        #pragma unroll
        for (int part = 0; part < NPART; part++) {
            const float* p = bt + (size_t)(part * 5) * NBIN;
            c0 += p[0];
            c1 += p[NBIN];
            c2 += p[2 * NBIN];
            c3 += p[3 * NBIN];
            c4 += p[4 * NBIN];
        }
        cf0[bin] = c0;
        cf4[bin] = make_float4(c1, c2, c3, c4);
    }
    __syncthreads();

    float mn = s_mm.x, mx = s_mm.y;
    float w = fmaxf(mx - mn, 1e-20f) * (1.0f / NBIN);

    const float L2E = 1.44269504088896340736f;
    int i = (ic << 7) + tid;
    float a  = 0.125f * g_Qs[((size_t)bh << 11) + i];   // natural-log domain
    float a2 = a * L2E;                                 // exp2 domain
    float nM = -((a2 >= 0.f) ? a2 * mx : a2 * mn);
    float rd = ex2f(a2 * w);                            // per-bin ratio

    float acc0 = 0.f, acc1 = 0.f;
    #pragma unroll 1
    for (int seg = 0; seg < 8; seg++) {
        float kb = fmaf((float)(seg * 32) + 0.5f, w, mn);
        float e  = ex2f(fmaf(a2, kb, nM));
        float accs = 0.f;
        #pragma unroll
        for (int t = 0; t < 32; t++) {
            int bIdx = seg * 32 + t;
            float4 c = cf4[bIdx];
            float p = fmaf(a, c.w, c.z);
            p = fmaf(a, p, c.y);
            p = fmaf(a, p, c.x);
            p = fmaf(a, p, cf0[bIdx]);
            accs = fmaf(e, p, accs);
            e *= rd;
        }
        if (seg & 1) acc1 += accs; else acc0 += accs;
    }
    float denom = acc0 + acc1;

    float ki  = g_Ks[((size_t)bh << 11) + i];
    float num = ex2f(fmaf(a2, ki, nM));
    g_diag[((size_t)bh << 11) + i] = num / denom;
}

// ---------------------------------------------------------------------------
// K4: Y[b,p,n] = sum_h diag[b,h,p] * Ut[b,n,h] + bias[n].
//   Register-tiled rank-16 GEMM: 256 threads x 4 consecutive n (STG.128),
//   p-tile 32; grid 256 = 4b x 64 p-tiles.
// ---------------------------------------------------------------------------
__global__ void __launch_bounds__(256) k_out(const float* __restrict__ bias,
                                             float* __restrict__ Y) {
    int pt = blockIdx.x & 63;
    int b  = blockIdx.x >> 6;
    int tid = threadIdx.x;
    __shared__ float dsm[HH * 32];
    #pragma unroll
    for (int r = 0; r < 2; r++) {
        int idx = r * 256 + tid;
        int h = idx >> 5, pl = idx & 31;
        dsm[h * 32 + pl] = g_diag[(((size_t)(b * HH + h)) << 11) + pt * 32 + pl];
    }
    __syncthreads();

    int n0 = tid << 2;
    float4 u4[HH];
    {
        const float4* up = (const float4*)(g_Ut + ((size_t)((b << 10) + n0)) * HH);
        float un[4][HH];
        #pragma unroll
        for (int nn = 0; nn < 4; nn++) {
            #pragma unroll
            for (int q = 0; q < 4; q++) {
                float4 v = up[nn * 4 + q];
                un[nn][4*q] = v.x; un[nn][4*q+1] = v.y;
                un[nn][4*q+2] = v.z; un[nn][4*q+3] = v.w;
            }
        }
        #pragma unroll
        for (int h = 0; h < HH; h++)
            u4[h] = make_float4(un[0][h], un[1][h], un[2][h], un[3][h]);
    }
    float4 bn = *(const float4*)(bias + n0);

    float4* out = (float4*)(Y + (((size_t)(b * PP + pt * 32)) << 10) + n0);
    #pragma unroll 2
    for (int p = 0; p < 32; p++) {
        float4 acc = bn;
        #pragma unroll
        for (int h = 0; h < HH; h++) {
            float d = dsm[h * 32 + p];
            acc.x = fmaf(u4[h].x, d, acc.x);
            acc.y = fmaf(u4[h].y, d, acc.y);
            acc.z = fmaf(u4[h].z, d, acc.z);
            acc.w = fmaf(u4[h].w, d, acc.w);
        }
        out[(size_t)p << 8] = acc;
    }
}

extern "C" void kernel_launch(void* const* d_in, const int* in_sizes, int n_in,
                              void* d_out, int out_size) {
    const float* Q    = (const float*)d_in[0];
    const float* K    = (const float*)d_in[1];
    const float* V    = (const float*)d_in[2];
    const float* W    = (const float*)d_in[3];
    const float* bias = (const float*)d_in[4];
    float* Y = (float*)d_out;

    k_reduce<<<16896, 256>>>(Q, K, V);
    k_mid<<<576, 256>>>(W);
    k_softmax_diag<<<1024, 128>>>();
    k_out<<<256, 256>>>(bias, Y);
}